// round 1
// baseline (speedup 1.0000x reference)
#include <cuda_runtime.h>
#include <cstdint>

// ---------------------------------------------------------------------------
// Problem: out = resize(patch_mean(conv3x3(x,gw,gb) + conv1x1(x,tw,tb), 7), HxW)
// All ops linear -> fold 1x1 into 3x3 center tap; patch_mean entries are
// rect-sums of feat; rect-sums of feat are weighted rect-sums of x; those
// derive from 81 border/total stats per (b,ci) plane. feat never materialized.
// ---------------------------------------------------------------------------

#define H 512
#define W 512
#define B_SZ 32
#define CIN 4
#define COUT 2
#define NPLANES (B_SZ * CIN)        // 128
#define NQ (B_SZ * COUT)            // 64
#define STATS_PER_PLANE 81          // [0]=T, [1..8]=rowsum(0..3,508..511),
                                    // [9..16]=colsum(0..3,508..511),
                                    // [17..80]=corner[r8][c8]
#define BLOCKS_PER_PLANE 64         // 8 rows per block
#define PART_PER_BLOCK 9            // T, colL[4], colR[4]

__device__ float g_stats[NPLANES * STATS_PER_PLANE];
__device__ float g_part[NPLANES * BLOCKS_PER_PLANE * PART_PER_BLOCK];
__device__ float g_m[NQ * 49];

// ---------------------------------------------------------------------------
// k1: per-plane reductions over x. grid (64, 128), block 256 (8 warps, 1 row/warp)
// Each lane loads 4 float4 (64B) of its row; fully coalesced; x read exactly once.
// Row sums + corner values are unique-writer plain stores (deterministic).
// T and col sums go to per-block partial slots (reduced deterministically in k1b).
// ---------------------------------------------------------------------------
__global__ void __launch_bounds__(256) k1_reduce(const float* __restrict__ x) {
    const int plane = blockIdx.y;
    const int rb    = blockIdx.x;
    const int warp  = threadIdx.x >> 5;
    const int lane  = threadIdx.x & 31;
    const int row   = rb * 8 + warp;

    const float4* r4 = reinterpret_cast<const float4*>(
        x + ((size_t)plane << 18) + (size_t)row * W);

    float4 v0 = r4[lane];
    float4 v1 = r4[lane + 32];
    float4 v2 = r4[lane + 64];
    float4 v3 = r4[lane + 96];

    float s = (v0.x + v0.y) + (v0.z + v0.w)
            + (v1.x + v1.y) + (v1.z + v1.w)
            + (v2.x + v2.y) + (v2.z + v2.w)
            + (v3.x + v3.y) + (v3.z + v3.w);
    #pragma unroll
    for (int o = 16; o > 0; o >>= 1)
        s += __shfl_down_sync(0xFFFFFFFFu, s, o);

    __shared__ float sT[8];
    __shared__ float sColL[8][4];
    __shared__ float sColR[8][4];

    int ridx = -1;
    if (row < 4) ridx = row;
    else if (row >= 508) ridx = row - 504;   // 508..511 -> 4..7
    float* st = &g_stats[plane * STATS_PER_PLANE];

    if (lane == 0) {
        sT[warp] = s;
        sColL[warp][0] = v0.x; sColL[warp][1] = v0.y;
        sColL[warp][2] = v0.z; sColL[warp][3] = v0.w;
        if (ridx >= 0) {
            st[1 + ridx] = s;                       // row sum
            st[17 + ridx * 8 + 0] = v0.x;           // corners c 0..3
            st[17 + ridx * 8 + 1] = v0.y;
            st[17 + ridx * 8 + 2] = v0.z;
            st[17 + ridx * 8 + 3] = v0.w;
        }
    }
    if (lane == 31) {
        sColR[warp][0] = v3.x; sColR[warp][1] = v3.y;
        sColR[warp][2] = v3.z; sColR[warp][3] = v3.w;
        if (ridx >= 0) {                            // f4 idx 127 = cols 508..511
            st[17 + ridx * 8 + 4] = v3.x;
            st[17 + ridx * 8 + 5] = v3.y;
            st[17 + ridx * 8 + 6] = v3.z;
            st[17 + ridx * 8 + 7] = v3.w;
        }
    }
    __syncthreads();

    if (threadIdx.x == 0) {
        float T = 0.f;
        float cl[4] = {0.f, 0.f, 0.f, 0.f};
        float cr[4] = {0.f, 0.f, 0.f, 0.f};
        #pragma unroll
        for (int w = 0; w < 8; w++) {
            T += sT[w];
            #pragma unroll
            for (int c = 0; c < 4; c++) { cl[c] += sColL[w][c]; cr[c] += sColR[w][c]; }
        }
        float* pp = &g_part[(plane * BLOCKS_PER_PLANE + rb) * PART_PER_BLOCK];
        pp[0] = T;
        #pragma unroll
        for (int c = 0; c < 4; c++) { pp[1 + c] = cl[c]; pp[5 + c] = cr[c]; }
    }
}

// ---------------------------------------------------------------------------
// k1b: deterministic tree reduction of 64 block-partials per plane.
// ---------------------------------------------------------------------------
__global__ void __launch_bounds__(64) k1b_reduce() {
    const int p = blockIdx.x;
    const int t = threadIdx.x;
    float v[PART_PER_BLOCK];
    const float* pp = &g_part[(p * BLOCKS_PER_PLANE + t) * PART_PER_BLOCK];
    #pragma unroll
    for (int k = 0; k < PART_PER_BLOCK; k++) v[k] = pp[k];

    __shared__ float red[64];
    float* st = &g_stats[p * STATS_PER_PLANE];
    #pragma unroll
    for (int k = 0; k < PART_PER_BLOCK; k++) {
        red[t] = v[k];
        __syncthreads();
        #pragma unroll
        for (int o = 32; o > 0; o >>= 1) {
            if (t < o) red[t] += red[t + o];
            __syncthreads();
        }
        if (t == 0) {
            float r = red[0];
            if (k == 0)      st[0] = r;             // T
            else if (k < 5)  st[9 + (k - 1)] = r;   // colsum left 0..3
            else             st[13 + (k - 5)] = r;  // colsum right (508..511)
        }
        __syncthreads();
    }
}

// ---------------------------------------------------------------------------
// k2: m[b,co,i,j] = (1/(H*W)) * [ bias*area + sum_{ci,tap} w' * RectX ]
// RectX via inclusion-exclusion over the 81 stats. grid 64, block 64.
// ---------------------------------------------------------------------------
__global__ void __launch_bounds__(64) k2_means(const float* __restrict__ gw,
                                               const float* __restrict__ gb,
                                               const float* __restrict__ tw,
                                               const float* __restrict__ tb) {
    const int b  = blockIdx.x >> 1;
    const int co = blockIdx.x & 1;
    const int tid = threadIdx.x;

    __shared__ float sT[CIN];
    __shared__ float rowPre[CIN][5], rowSuf[CIN][5];
    __shared__ float colPre[CIN][5], colSuf[CIN][5];
    __shared__ float cTL[CIN][5][5], cTR[CIN][5][5], cBL[CIN][5][5], cBR[CIN][5][5];
    __shared__ float wc[CIN][9];
    __shared__ float biasS;

    if (tid < CIN) {
        const int ci = tid;
        const float* st = &g_stats[(b * CIN + ci) * STATS_PER_PLANE];
        sT[ci] = st[0];
        rowPre[ci][0] = 0.f; rowSuf[ci][0] = 0.f;
        colPre[ci][0] = 0.f; colSuf[ci][0] = 0.f;
        for (int n = 1; n <= 4; n++) {
            rowPre[ci][n] = rowPre[ci][n - 1] + st[1 + (n - 1)];
            rowSuf[ci][n] = rowSuf[ci][n - 1] + st[1 + (7 - (n - 1))];
            colPre[ci][n] = colPre[ci][n - 1] + st[9 + (n - 1)];
            colSuf[ci][n] = colSuf[ci][n - 1] + st[9 + (7 - (n - 1))];
        }
        // corner 2D prefixes (tiny; indices: top rows r=0..3, bottom rows idx 7-t)
        for (int a = 0; a < 5; a++)
            for (int bb = 0; bb < 5; bb++) {
                float tl = 0.f, tr = 0.f, bl = 0.f, br = 0.f;
                for (int r = 0; r < a; r++)
                    for (int c = 0; c < bb; c++) {
                        tl += st[17 + r * 8 + c];
                        tr += st[17 + r * 8 + (7 - c)];
                        bl += st[17 + (7 - r) * 8 + c];
                        br += st[17 + (7 - r) * 8 + (7 - c)];
                    }
                cTL[ci][a][bb] = tl; cTR[ci][a][bb] = tr;
                cBL[ci][a][bb] = bl; cBR[ci][a][bb] = br;
            }
    }
    if (tid < CIN * 9) {
        const int ci = tid / 9, tap = tid % 9;
        float w = gw[(co * CIN + ci) * 9 + tap];
        if (tap == 4) w += tw[co * CIN + ci];    // fold 1x1 into center tap
        wc[ci][tap] = w;
    }
    if (tid == 0) biasS = gb[co] + tb[co];
    __syncthreads();

    if (tid < 49) {
        const int i = tid / 7, j = tid % 7;
        const int r0 = max(0, i - 3), r1 = 509 + min(i, 3);
        const int c0 = max(0, j - 3), c1 = 509 + min(j, 3);
        float acc = biasS * (float)((r1 - r0) * (c1 - c0));
        #pragma unroll
        for (int ci = 0; ci < CIN; ci++) {
            #pragma unroll
            for (int di = 0; di < 3; di++) {
                const int rr0 = max(0, r0 + di - 1);
                const int rr1 = min(H, r1 + di - 1);
                const int nB  = H - rr1;
                #pragma unroll
                for (int dj = 0; dj < 3; dj++) {
                    const int cc0 = max(0, c0 + dj - 1);
                    const int cc1 = min(W, c1 + dj - 1);
                    const int nR  = W - cc1;
                    float rect = sT[ci]
                               - rowPre[ci][rr0] - rowSuf[ci][nB]
                               - colPre[ci][cc0] - colSuf[ci][nR]
                               + cTL[ci][rr0][cc0] + cTR[ci][rr0][nR]
                               + cBL[ci][nB][cc0]  + cBR[ci][nB][nR];
                    acc += wc[ci][di * 3 + dj] * rect;
                }
            }
        }
        g_m[blockIdx.x * 49 + tid] = acc * (1.0f / (float)(H * W));
    }
}

// ---------------------------------------------------------------------------
// k3: clamped bilinear 7x7 -> 512x512 (== jax half-pixel normalized resize).
// grid (256, 64), block 256, one float4 per thread. Write-bandwidth bound.
// ---------------------------------------------------------------------------
__global__ void __launch_bounds__(256) k3_upsample(float* __restrict__ out) {
    const int q = blockIdx.y;                      // b*2+co
    __shared__ float sm[49];
    if (threadIdx.x < 49) sm[threadIdx.x] = g_m[q * 49 + threadIdx.x];
    __syncthreads();

    const int f4 = blockIdx.x * blockDim.x + threadIdx.x;  // 0..65535
    const int h  = f4 >> 7;
    const int w0 = (f4 & 127) << 2;

    const float S = 7.0f / 512.0f;
    float hs = ((float)h + 0.5f) * S - 0.5f;
    float ihf = floorf(hs);
    float fh = hs - ihf;
    int ih = (int)ihf;
    int ih0 = max(ih, 0), ih1 = min(ih + 1, 6);
    const float* rA = &sm[ih0 * 7];
    const float* rB = &sm[ih1 * 7];

    float4 o;
    float* op = &o.x;
    #pragma unroll
    for (int c = 0; c < 4; c++) {
        float ws = ((float)(w0 + c) + 0.5f) * S - 0.5f;
        float iwf = floorf(ws);
        float fw = ws - iwf;
        int iw = (int)iwf;
        int iw0 = max(iw, 0), iw1 = min(iw + 1, 6);
        float top = rA[iw0] + fw * (rA[iw1] - rA[iw0]);
        float bot = rB[iw0] + fw * (rB[iw1] - rB[iw0]);
        op[c] = top + fh * (bot - top);
    }
    reinterpret_cast<float4*>(out)[((size_t)q << 16) + f4] = o;
}

// ---------------------------------------------------------------------------
extern "C" void kernel_launch(void* const* d_in, const int* in_sizes, int n_in,
                              void* d_out, int out_size) {
    const float* x  = (const float*)d_in[0];   // [32,4,512,512]
    const float* gw = (const float*)d_in[1];   // [2,4,3,3]
    const float* gb = (const float*)d_in[2];   // [2]
    const float* tw = (const float*)d_in[3];   // [2,4,1,1]
    const float* tb = (const float*)d_in[4];   // [2]
    float* out = (float*)d_out;                // [32,2,512,512]

    k1_reduce<<<dim3(BLOCKS_PER_PLANE, NPLANES), 256>>>(x);
    k1b_reduce<<<NPLANES, 64>>>();
    k2_means<<<NQ, 64>>>(gw, gb, tw, tb);
    k3_upsample<<<dim3(256, NQ), 256>>>(out);
}

// round 2
// speedup vs baseline: 1.1238x; 1.1238x over previous
#include <cuda_runtime.h>
#include <cstdint>

// ---------------------------------------------------------------------------
// out = resize(patch_mean(conv3x3(x,gw,gb) + conv1x1(x,tw,tb), 7), HxW)
// Linear algebra reduction: feat never materialized; 81 border/total stats per
// (b,ci) plane -> 49 patch means -> factored bilinear (precomputed col-interp
// rows) -> pure lerp-and-store upsample kernel.
// ---------------------------------------------------------------------------

#define H 512
#define W 512
#define B_SZ 32
#define CIN 4
#define COUT 2
#define NPLANES (B_SZ * CIN)        // 128
#define NQ (B_SZ * COUT)            // 64
#define STATS_PER_PLANE 81          // [0]=T, [1..8]=rowsum(0..3,508..511),
                                    // [9..16]=colsum(0..3,508..511),
                                    // [17..80]=corner[r8][c8]
#define BLOCKS_PER_PLANE 64         // 8 rows per block
#define PART_PER_BLOCK 9            // T, colL[4], colR[4]

__device__ float g_stats[NPLANES * STATS_PER_PLANE];
__device__ float g_part[NPLANES * BLOCKS_PER_PLANE * PART_PER_BLOCK];
__device__ __align__(16) float g_rows[NQ * 7 * W];   // col-interpolated rows

// ---------------------------------------------------------------------------
// k1: per-plane reductions over x. grid (64, 128), block 256 (8 warps, 1 row/warp)
// x read exactly once, fully coalesced. Unique-writer stores -> deterministic.
// ---------------------------------------------------------------------------
__global__ void __launch_bounds__(256) k1_reduce(const float* __restrict__ x) {
    const int plane = blockIdx.y;
    const int rb    = blockIdx.x;
    const int warp  = threadIdx.x >> 5;
    const int lane  = threadIdx.x & 31;
    const int row   = rb * 8 + warp;

    const float4* r4 = reinterpret_cast<const float4*>(
        x + ((size_t)plane << 18) + (size_t)row * W);

    float4 v0 = r4[lane];
    float4 v1 = r4[lane + 32];
    float4 v2 = r4[lane + 64];
    float4 v3 = r4[lane + 96];

    float s = (v0.x + v0.y) + (v0.z + v0.w)
            + (v1.x + v1.y) + (v1.z + v1.w)
            + (v2.x + v2.y) + (v2.z + v2.w)
            + (v3.x + v3.y) + (v3.z + v3.w);
    #pragma unroll
    for (int o = 16; o > 0; o >>= 1)
        s += __shfl_down_sync(0xFFFFFFFFu, s, o);

    __shared__ float sT[8];
    __shared__ float sColL[8][4];
    __shared__ float sColR[8][4];

    int ridx = -1;
    if (row < 4) ridx = row;
    else if (row >= 508) ridx = row - 504;   // 508..511 -> 4..7
    float* st = &g_stats[plane * STATS_PER_PLANE];

    if (lane == 0) {
        sT[warp] = s;
        sColL[warp][0] = v0.x; sColL[warp][1] = v0.y;
        sColL[warp][2] = v0.z; sColL[warp][3] = v0.w;
        if (ridx >= 0) {
            st[1 + ridx] = s;
            st[17 + ridx * 8 + 0] = v0.x;
            st[17 + ridx * 8 + 1] = v0.y;
            st[17 + ridx * 8 + 2] = v0.z;
            st[17 + ridx * 8 + 3] = v0.w;
        }
    }
    if (lane == 31) {
        sColR[warp][0] = v3.x; sColR[warp][1] = v3.y;
        sColR[warp][2] = v3.z; sColR[warp][3] = v3.w;
        if (ridx >= 0) {
            st[17 + ridx * 8 + 4] = v3.x;
            st[17 + ridx * 8 + 5] = v3.y;
            st[17 + ridx * 8 + 6] = v3.z;
            st[17 + ridx * 8 + 7] = v3.w;
        }
    }
    __syncthreads();

    if (threadIdx.x == 0) {
        float T = 0.f;
        float cl[4] = {0.f, 0.f, 0.f, 0.f};
        float cr[4] = {0.f, 0.f, 0.f, 0.f};
        #pragma unroll
        for (int w = 0; w < 8; w++) {
            T += sT[w];
            #pragma unroll
            for (int c = 0; c < 4; c++) { cl[c] += sColL[w][c]; cr[c] += sColR[w][c]; }
        }
        float* pp = &g_part[(plane * BLOCKS_PER_PLANE + rb) * PART_PER_BLOCK];
        pp[0] = T;
        #pragma unroll
        for (int c = 0; c < 4; c++) { pp[1 + c] = cl[c]; pp[5 + c] = cr[c]; }
    }
}

// ---------------------------------------------------------------------------
// kmid: fused (partial-reduce + means + column-interp row precompute).
// grid 64 (one block per q=(b,co)), block 256.
// ---------------------------------------------------------------------------
__global__ void __launch_bounds__(256) kmid(const float* __restrict__ gw,
                                            const float* __restrict__ gb,
                                            const float* __restrict__ tw,
                                            const float* __restrict__ tb) {
    const int q  = blockIdx.x;
    const int b  = q >> 1;
    const int co = q & 1;
    const int tid = threadIdx.x;

    __shared__ float st[CIN][STATS_PER_PLANE];
    __shared__ float red[256];
    __shared__ float rowPre[CIN][5], rowSuf[CIN][5];
    __shared__ float colPre[CIN][5], colSuf[CIN][5];
    __shared__ float cTL[CIN][5][5], cTR[CIN][5][5], cBL[CIN][5][5], cBR[CIN][5][5];
    __shared__ float wc[CIN][9];
    __shared__ float biasS;
    __shared__ float sm_m[49];

    // stage k1's per-plane stats (row sums + corners valid; T/colsums redone below)
    for (int i = tid; i < CIN * STATS_PER_PLANE; i += 256)
        st[i / STATS_PER_PLANE][i % STATS_PER_PLANE] =
            g_stats[(size_t)(b * CIN) * STATS_PER_PLANE + i];
    __syncthreads();

    // deterministic tree-reduce of 64 block-partials for all 4 planes in parallel
    const int ci = tid >> 6;
    const int t  = tid & 63;
    const float* pp = &g_part[((b * CIN + ci) * BLOCKS_PER_PLANE + t) * PART_PER_BLOCK];
    float v[PART_PER_BLOCK];
    #pragma unroll
    for (int k = 0; k < PART_PER_BLOCK; k++) v[k] = pp[k];

    #pragma unroll
    for (int k = 0; k < PART_PER_BLOCK; k++) {
        red[tid] = v[k];
        __syncthreads();
        #pragma unroll
        for (int o = 32; o > 0; o >>= 1) {
            if (t < o) red[tid] += red[tid + o];
            __syncthreads();
        }
        if (t == 0) {
            float r = red[tid];
            if (k == 0)      st[ci][0] = r;
            else if (k < 5)  st[ci][9 + (k - 1)] = r;
            else             st[ci][13 + (k - 5)] = r;
        }
        __syncthreads();
    }

    // prefixes for inclusion-exclusion
    if (tid < CIN) {
        const int c = tid;
        rowPre[c][0] = 0.f; rowSuf[c][0] = 0.f;
        colPre[c][0] = 0.f; colSuf[c][0] = 0.f;
        for (int n = 1; n <= 4; n++) {
            rowPre[c][n] = rowPre[c][n - 1] + st[c][1 + (n - 1)];
            rowSuf[c][n] = rowSuf[c][n - 1] + st[c][1 + (7 - (n - 1))];
            colPre[c][n] = colPre[c][n - 1] + st[c][9 + (n - 1)];
            colSuf[c][n] = colSuf[c][n - 1] + st[c][9 + (7 - (n - 1))];
        }
        for (int a = 0; a < 5; a++)
            for (int bb = 0; bb < 5; bb++) {
                float tl = 0.f, tr = 0.f, bl = 0.f, br = 0.f;
                for (int r = 0; r < a; r++)
                    for (int cc = 0; cc < bb; cc++) {
                        tl += st[c][17 + r * 8 + cc];
                        tr += st[c][17 + r * 8 + (7 - cc)];
                        bl += st[c][17 + (7 - r) * 8 + cc];
                        br += st[c][17 + (7 - r) * 8 + (7 - cc)];
                    }
                cTL[c][a][bb] = tl; cTR[c][a][bb] = tr;
                cBL[c][a][bb] = bl; cBR[c][a][bb] = br;
            }
    }
    if (tid < CIN * 9) {
        const int c = tid / 9, tap = tid % 9;
        float w = gw[(co * CIN + c) * 9 + tap];
        if (tap == 4) w += tw[co * CIN + c];    // fold 1x1 into center tap
        wc[c][tap] = w;
    }
    if (tid == 0) biasS = gb[co] + tb[co];
    __syncthreads();

    // 49 patch means
    if (tid < 49) {
        const int i = tid / 7, j = tid % 7;
        const int r0 = max(0, i - 3), r1 = 509 + min(i, 3);
        const int c0 = max(0, j - 3), c1 = 509 + min(j, 3);
        float acc = biasS * (float)((r1 - r0) * (c1 - c0));
        #pragma unroll
        for (int c = 0; c < CIN; c++) {
            #pragma unroll
            for (int di = 0; di < 3; di++) {
                const int rr0 = max(0, r0 + di - 1);
                const int rr1 = min(H, r1 + di - 1);
                const int nB  = H - rr1;
                #pragma unroll
                for (int dj = 0; dj < 3; dj++) {
                    const int cc0 = max(0, c0 + dj - 1);
                    const int cc1 = min(W, c1 + dj - 1);
                    const int nR  = W - cc1;
                    float rect = st[c][0]
                               - rowPre[c][rr0] - rowSuf[c][nB]
                               - colPre[c][cc0] - colSuf[c][nR]
                               + cTL[c][rr0][cc0] + cTR[c][rr0][nR]
                               + cBL[c][nB][cc0]  + cBR[c][nB][nR];
                    acc += wc[c][di * 3 + dj] * rect;
                }
            }
        }
        sm_m[tid] = acc * (1.0f / (float)(H * W));
    }
    __syncthreads();

    // precompute column-interpolated rows: rows[q][i][w], i in 0..6, w in 0..511
    const float S = 7.0f / 512.0f;
    for (int idx = tid; idx < 7 * W; idx += 256) {
        const int i = idx >> 9;
        const int w = idx & (W - 1);
        float ws = ((float)w + 0.5f) * S - 0.5f;
        float iwf = floorf(ws);
        float fw = ws - iwf;
        int iw = (int)iwf;
        int iw0 = max(iw, 0), iw1 = min(iw + 1, 6);
        const float* r = &sm_m[i * 7];
        g_rows[q * (7 * W) + idx] = fmaf(fw, r[iw1] - r[iw0], r[iw0]);
    }
}

// ---------------------------------------------------------------------------
// k3: pure row-lerp upsample. grid (16, 64), block 256, 16 float4/thread.
// Per float4: 2 LDS.128 + 4 FMA + 1 STG.128 (+ tiny row math).
// ---------------------------------------------------------------------------
__global__ void __launch_bounds__(256) k3_upsample(float* __restrict__ out) {
    const int q = blockIdx.y;
    __shared__ __align__(16) float rows[7 * W];

    const float4* gr4 = reinterpret_cast<const float4*>(&g_rows[q * (7 * W)]);
    float4* sr4 = reinterpret_cast<float4*>(rows);
    for (int i = threadIdx.x; i < (7 * W) / 4; i += 256) sr4[i] = gr4[i];
    __syncthreads();

    const float4* rows4 = reinterpret_cast<const float4*>(rows);
    float4* out4 = reinterpret_cast<float4*>(out) + ((size_t)q << 16);

    const float S = 7.0f / 512.0f;
    const int base = blockIdx.x * 4096 + threadIdx.x;

    #pragma unroll
    for (int k = 0; k < 16; k++) {
        const int f4 = base + k * 256;
        const int h  = f4 >> 7;
        const int w4 = f4 & 127;

        float hs = ((float)h + 0.5f) * S - 0.5f;
        float ihf = floorf(hs);
        float fh = hs - ihf;
        int ih = (int)ihf;
        int ih0 = max(ih, 0), ih1 = min(ih + 1, 6);

        float4 a  = rows4[ih0 * 128 + w4];
        float4 bb = rows4[ih1 * 128 + w4];
        float4 o;
        o.x = fmaf(fh, bb.x - a.x, a.x);
        o.y = fmaf(fh, bb.y - a.y, a.y);
        o.z = fmaf(fh, bb.z - a.z, a.z);
        o.w = fmaf(fh, bb.w - a.w, a.w);
        out4[f4] = o;
    }
}

// ---------------------------------------------------------------------------
extern "C" void kernel_launch(void* const* d_in, const int* in_sizes, int n_in,
                              void* d_out, int out_size) {
    const float* x  = (const float*)d_in[0];   // [32,4,512,512]
    const float* gw = (const float*)d_in[1];   // [2,4,3,3]
    const float* gb = (const float*)d_in[2];   // [2]
    const float* tw = (const float*)d_in[3];   // [2,4,1,1]
    const float* tb = (const float*)d_in[4];   // [2]
    float* out = (float*)d_out;                // [32,2,512,512]

    k1_reduce<<<dim3(BLOCKS_PER_PLANE, NPLANES), 256>>>(x);
    kmid<<<NQ, 256>>>(gw, gb, tw, tb);
    k3_upsample<<<dim3(16, NQ), 256>>>(out);
}

// round 3
// speedup vs baseline: 1.3346x; 1.1875x over previous
#include <cuda_runtime.h>
#include <cstdint>

// ---------------------------------------------------------------------------
// out = resize(patch_mean(conv3x3(x,gw,gb) + conv1x1(x,tw,tb), 7), HxW)
// Linear algebra reduction: feat never materialized; 81 border/total stats per
// (b,ci) plane -> 49 patch means -> factored bilinear (precomputed col-interp
// rows) -> pure lerp-and-store upsample kernel.
// ---------------------------------------------------------------------------

#define H 512
#define W 512
#define B_SZ 32
#define CIN 4
#define COUT 2
#define NPLANES (B_SZ * CIN)        // 128
#define NQ (B_SZ * COUT)            // 64
#define STATS_PER_PLANE 81          // [0]=T, [1..8]=rowsum(0..3,508..511),
                                    // [9..16]=colsum(0..3,508..511),
                                    // [17..80]=corner[r8][c8]
#define BLOCKS_PER_PLANE 64         // 8 rows per block
#define PART_PER_BLOCK 9            // T, colL[4], colR[4]

__device__ float g_stats[NPLANES * STATS_PER_PLANE];
__device__ float g_part[NPLANES * BLOCKS_PER_PLANE * PART_PER_BLOCK];
__device__ __align__(16) float g_rows[NQ * 7 * W];   // col-interpolated rows

// ---------------------------------------------------------------------------
// k1: per-plane reductions over x. grid (64, 128), block 256 (8 warps, 1 row/warp)
// x read exactly once (streaming .cs), fully coalesced. Unique-writer stores.
// ---------------------------------------------------------------------------
__global__ void __launch_bounds__(256) k1_reduce(const float* __restrict__ x) {
    const int plane = blockIdx.y;
    const int rb    = blockIdx.x;
    const int warp  = threadIdx.x >> 5;
    const int lane  = threadIdx.x & 31;
    const int row   = rb * 8 + warp;

    const float4* r4 = reinterpret_cast<const float4*>(
        x + ((size_t)plane << 18) + (size_t)row * W);

    float4 v0 = __ldcs(r4 + lane);
    float4 v1 = __ldcs(r4 + lane + 32);
    float4 v2 = __ldcs(r4 + lane + 64);
    float4 v3 = __ldcs(r4 + lane + 96);

    float s = (v0.x + v0.y) + (v0.z + v0.w)
            + (v1.x + v1.y) + (v1.z + v1.w)
            + (v2.x + v2.y) + (v2.z + v2.w)
            + (v3.x + v3.y) + (v3.z + v3.w);
    #pragma unroll
    for (int o = 16; o > 0; o >>= 1)
        s += __shfl_down_sync(0xFFFFFFFFu, s, o);

    __shared__ float sT[8];
    __shared__ float sColL[8][4];
    __shared__ float sColR[8][4];

    int ridx = -1;
    if (row < 4) ridx = row;
    else if (row >= 508) ridx = row - 504;   // 508..511 -> 4..7
    float* st = &g_stats[plane * STATS_PER_PLANE];

    if (lane == 0) {
        sT[warp] = s;
        sColL[warp][0] = v0.x; sColL[warp][1] = v0.y;
        sColL[warp][2] = v0.z; sColL[warp][3] = v0.w;
        if (ridx >= 0) {
            st[1 + ridx] = s;
            st[17 + ridx * 8 + 0] = v0.x;
            st[17 + ridx * 8 + 1] = v0.y;
            st[17 + ridx * 8 + 2] = v0.z;
            st[17 + ridx * 8 + 3] = v0.w;
        }
    }
    if (lane == 31) {
        sColR[warp][0] = v3.x; sColR[warp][1] = v3.y;
        sColR[warp][2] = v3.z; sColR[warp][3] = v3.w;
        if (ridx >= 0) {
            st[17 + ridx * 8 + 4] = v3.x;
            st[17 + ridx * 8 + 5] = v3.y;
            st[17 + ridx * 8 + 6] = v3.z;
            st[17 + ridx * 8 + 7] = v3.w;
        }
    }
    __syncthreads();

    if (threadIdx.x == 0) {
        float T = 0.f;
        float cl[4] = {0.f, 0.f, 0.f, 0.f};
        float cr[4] = {0.f, 0.f, 0.f, 0.f};
        #pragma unroll
        for (int w = 0; w < 8; w++) {
            T += sT[w];
            #pragma unroll
            for (int c = 0; c < 4; c++) { cl[c] += sColL[w][c]; cr[c] += sColR[w][c]; }
        }
        float* pp = &g_part[(plane * BLOCKS_PER_PLANE + rb) * PART_PER_BLOCK];
        pp[0] = T;
        #pragma unroll
        for (int c = 0; c < 4; c++) { pp[1 + c] = cl[c]; pp[5 + c] = cr[c]; }
    }
}

// ---------------------------------------------------------------------------
// kmid: fused (partial-reduce + means + column-interp row precompute).
// grid 64 (one block per q=(b,co)), block 256. Warp-shuffle reductions
// (no smem tree), fully parallel corner prefixes.
// ---------------------------------------------------------------------------
__global__ void __launch_bounds__(256) kmid(const float* __restrict__ gw,
                                            const float* __restrict__ gb,
                                            const float* __restrict__ tw,
                                            const float* __restrict__ tb) {
    const int q  = blockIdx.x;
    const int b  = q >> 1;
    const int co = q & 1;
    const int tid  = threadIdx.x;
    const int warp = tid >> 5;
    const int lane = tid & 31;

    __shared__ float st[CIN][STATS_PER_PLANE];
    __shared__ float rowPre[CIN][5], rowSuf[CIN][5];
    __shared__ float colPre[CIN][5], colSuf[CIN][5];
    __shared__ float cTL[CIN][5][5], cTR[CIN][5][5], cBL[CIN][5][5], cBR[CIN][5][5];
    __shared__ float wc[CIN][9];
    __shared__ float biasS;
    __shared__ float sm_m[49];

    // stage k1's per-plane stats (row sums + corners valid; T/colsums redone)
    for (int i = tid; i < CIN * STATS_PER_PLANE; i += 256)
        st[i / STATS_PER_PLANE][i % STATS_PER_PLANE] =
            g_stats[(size_t)(b * CIN) * STATS_PER_PLANE + i];
    __syncthreads();

    // warp-shuffle reduce of 64 block-partials: 36 tasks (ci, k) over 8 warps
    for (int task = warp; task < CIN * PART_PER_BLOCK; task += 8) {
        const int ci = task / PART_PER_BLOCK;
        const int k  = task % PART_PER_BLOCK;
        const float* pb = &g_part[(size_t)(b * CIN + ci) * BLOCKS_PER_PLANE * PART_PER_BLOCK + k];
        float v = pb[(size_t)lane * PART_PER_BLOCK] + pb[(size_t)(lane + 32) * PART_PER_BLOCK];
        #pragma unroll
        for (int o = 16; o > 0; o >>= 1)
            v += __shfl_down_sync(0xFFFFFFFFu, v, o);
        if (lane == 0) {
            if (k == 0)      st[ci][0] = v;             // T
            else if (k < 5)  st[ci][9 + (k - 1)] = v;   // colsum left
            else             st[ci][13 + (k - 5)] = v;  // colsum right
        }
    }
    __syncthreads();

    // 1D prefixes (tiny, 16 threads) and 2D corner prefixes (100 threads)
    if (tid < CIN * 4) {
        const int c = tid >> 2, which = tid & 3;
        float a0 = 0.f, a1, a2, a3, a4;
        const int base = (which < 2) ? 1 : 9;           // row vs col sums
        const bool suf = (which & 1);
        float* dst = (which == 0) ? rowPre[c] : (which == 1) ? rowSuf[c]
                   : (which == 2) ? colPre[c] : colSuf[c];
        a1 = a0 + st[c][base + (suf ? 7 : 0)];
        a2 = a1 + st[c][base + (suf ? 6 : 1)];
        a3 = a2 + st[c][base + (suf ? 5 : 2)];
        a4 = a3 + st[c][base + (suf ? 4 : 3)];
        dst[0] = a0; dst[1] = a1; dst[2] = a2; dst[3] = a3; dst[4] = a4;
    }
    if (tid >= 32 && tid < 32 + CIN * 25) {
        const int u = tid - 32;
        const int c = u / 25, rem = u % 25;
        const int a = rem / 5, bb = rem % 5;
        float tl = 0.f, tr = 0.f, bl = 0.f, br = 0.f;
        for (int r = 0; r < a; r++)
            for (int cc = 0; cc < bb; cc++) {
                tl += st[c][17 + r * 8 + cc];
                tr += st[c][17 + r * 8 + (7 - cc)];
                bl += st[c][17 + (7 - r) * 8 + cc];
                br += st[c][17 + (7 - r) * 8 + (7 - cc)];
            }
        cTL[c][a][bb] = tl; cTR[c][a][bb] = tr;
        cBL[c][a][bb] = bl; cBR[c][a][bb] = br;
    }
    if (tid >= 160 && tid < 160 + CIN * 9) {
        const int u = tid - 160;
        const int c = u / 9, tap = u % 9;
        float w = gw[(co * CIN + c) * 9 + tap];
        if (tap == 4) w += tw[co * CIN + c];    // fold 1x1 into center tap
        wc[c][tap] = w;
    }
    if (tid == 255) biasS = gb[co] + tb[co];
    __syncthreads();

    // 49 patch means
    if (tid < 49) {
        const int i = tid / 7, j = tid % 7;
        const int r0 = max(0, i - 3), r1 = 509 + min(i, 3);
        const int c0 = max(0, j - 3), c1 = 509 + min(j, 3);
        float acc = biasS * (float)((r1 - r0) * (c1 - c0));
        #pragma unroll
        for (int c = 0; c < CIN; c++) {
            #pragma unroll
            for (int di = 0; di < 3; di++) {
                const int rr0 = max(0, r0 + di - 1);
                const int rr1 = min(H, r1 + di - 1);
                const int nB  = H - rr1;
                #pragma unroll
                for (int dj = 0; dj < 3; dj++) {
                    const int cc0 = max(0, c0 + dj - 1);
                    const int cc1 = min(W, c1 + dj - 1);
                    const int nR  = W - cc1;
                    float rect = st[c][0]
                               - rowPre[c][rr0] - rowSuf[c][nB]
                               - colPre[c][cc0] - colSuf[c][nR]
                               + cTL[c][rr0][cc0] + cTR[c][rr0][nR]
                               + cBL[c][nB][cc0]  + cBR[c][nB][nR];
                    acc += wc[c][di * 3 + dj] * rect;
                }
            }
        }
        sm_m[tid] = acc * (1.0f / (float)(H * W));
    }
    __syncthreads();

    // precompute column-interpolated rows: rows[q][i][w]
    const float S = 7.0f / 512.0f;
    for (int idx = tid; idx < 7 * W; idx += 256) {
        const int i = idx >> 9;
        const int w = idx & (W - 1);
        float ws = ((float)w + 0.5f) * S - 0.5f;
        float iwf = floorf(ws);
        float fw = ws - iwf;
        int iw = (int)iwf;
        int iw0 = max(iw, 0), iw1 = min(iw + 1, 6);
        const float* r = &sm_m[i * 7];
        g_rows[q * (7 * W) + idx] = fmaf(fw, r[iw1] - r[iw0], r[iw0]);
    }
}

// ---------------------------------------------------------------------------
// k3: pure row-lerp upsample. grid (16, 64), block 256, 16 float4/thread.
// ---------------------------------------------------------------------------
__global__ void __launch_bounds__(256) k3_upsample(float* __restrict__ out) {
    const int q = blockIdx.y;
    __shared__ __align__(16) float rows[7 * W];

    const float4* gr4 = reinterpret_cast<const float4*>(&g_rows[q * (7 * W)]);
    float4* sr4 = reinterpret_cast<float4*>(rows);
    for (int i = threadIdx.x; i < (7 * W) / 4; i += 256) sr4[i] = gr4[i];
    __syncthreads();

    const float4* rows4 = reinterpret_cast<const float4*>(rows);
    float4* out4 = reinterpret_cast<float4*>(out) + ((size_t)q << 16);

    const float S = 7.0f / 512.0f;
    const int base = blockIdx.x * 4096 + threadIdx.x;

    #pragma unroll
    for (int k = 0; k < 16; k++) {
        const int f4 = base + k * 256;
        const int h  = f4 >> 7;
        const int w4 = f4 & 127;

        float hs = ((float)h + 0.5f) * S - 0.5f;
        float ihf = floorf(hs);
        float fh = hs - ihf;
        int ih = (int)ihf;
        int ih0 = max(ih, 0), ih1 = min(ih + 1, 6);

        float4 a  = rows4[ih0 * 128 + w4];
        float4 bb = rows4[ih1 * 128 + w4];
        float4 o;
        o.x = fmaf(fh, bb.x - a.x, a.x);
        o.y = fmaf(fh, bb.y - a.y, a.y);
        o.z = fmaf(fh, bb.z - a.z, a.z);
        o.w = fmaf(fh, bb.w - a.w, a.w);
        out4[f4] = o;
    }
}

// ---------------------------------------------------------------------------
extern "C" void kernel_launch(void* const* d_in, const int* in_sizes, int n_in,
                              void* d_out, int out_size) {
    const float* x  = (const float*)d_in[0];   // [32,4,512,512]
    const float* gw = (const float*)d_in[1];   // [2,4,3,3]
    const float* gb = (const float*)d_in[2];   // [2]
    const float* tw = (const float*)d_in[3];   // [2,4,1,1]
    const float* tb = (const float*)d_in[4];   // [2]
    float* out = (float*)d_out;                // [32,2,512,512]

    k1_reduce<<<dim3(BLOCKS_PER_PLANE, NPLANES), 256>>>(x);
    kmid<<<NQ, 256>>>(gw, gb, tw, tb);
    k3_upsample<<<dim3(16, NQ), 256>>>(out);
}